// round 14
// baseline (speedup 1.0000x reference)
#include <cuda_runtime.h>
#include <cuda_fp16.h>
#include <cstdint>

// ---------------- problem constants ----------------
#define T_TOK 8192
#define D_DIM 2048
#define H_DIM 2048
#define NEXP  7
#define TOPK  3

// ---------------- tiling ----------------
#define BM 128
#define BN 128
#define BM2 256                // gemm2 M-tile
#define BKH 64                 // K-chunk in halfs (128B per row)
#define NTHREADS 512
#define XSTRH 72               // halfs per smem row (padded; conflict-free)
#define NIT (D_DIM / BKH)      // 32 k-iterations

#define TILE_B (128 * XSTRH * 2)        // bytes per 128-row tile = 18432
#define TILE_A2B (256 * XSTRH * 2)      // bytes per 256-row tile = 36864
#define STAGE1B (3 * TILE_B)            // gemm1 stage (A + B1 + Bg) = 55296
#define STAGE2B (TILE_A2B + TILE_B)     // gemm2 stage (A256 + B128) = 55296
#define NS1 3
#define NS2 3
#define SMEM1_BYTES (NS1 * STAGE1B)     // 165888
#define SMEM2_BYTES (NS2 * STAGE2B)     // 165888

#define WELEMS ((size_t)NEXP * D_DIM * H_DIM)
#define SELEMS ((size_t)D_DIM * H_DIM)
#define XELEMS ((size_t)T_TOK * D_DIM)

// ---------------- device scratch (no allocations allowed) ----------------
__device__ int   g_cnt[NEXP];
__device__ __align__(16) int   g_idx[NEXP][T_TOK];
__device__ int   g_te[T_TOK][TOPK];
__device__ int   g_tp[T_TOK][TOPK];
__device__ float g_tw[T_TOK][TOPK];

__device__ __align__(16) __half g_acth[8][(size_t)T_TOK * H_DIM];   // fp16 SwiGLU acts
__device__ __align__(16) __half g_y[NEXP][(size_t)T_TOK * D_DIM];   // staged routed outputs (fp16)

// fp16 operands: weights TRANSPOSED to [n][k]; x row-major [m][k]
__device__ __align__(16) __half g_w1h[WELEMS];
__device__ __align__(16) __half g_wgh[WELEMS];
__device__ __align__(16) __half g_w2h[WELEMS];
__device__ __align__(16) __half g_ws1h[SELEMS];
__device__ __align__(16) __half g_wsgh[SELEMS];
__device__ __align__(16) __half g_ws2h[SELEMS];
__device__ __align__(16) __half g_xh[XELEMS];

// ---------------- helpers ----------------
__device__ __forceinline__ float silu_f(float z) {
    return z / (1.0f + __expf(-z));
}

__device__ __forceinline__ void mma_f16(float c[4], const uint32_t a[4],
                                        const uint32_t b0, const uint32_t b1) {
    asm volatile(
        "mma.sync.aligned.m16n8k16.row.col.f32.f16.f16.f32 "
        "{%0,%1,%2,%3}, {%4,%5,%6,%7}, {%8,%9}, {%0,%1,%2,%3};\n"
        : "+f"(c[0]), "+f"(c[1]), "+f"(c[2]), "+f"(c[3])
        : "r"(a[0]), "r"(a[1]), "r"(a[2]), "r"(a[3]),
          "r"(b0), "r"(b1));
}

#define LDSM4(r, addr) \
    asm volatile("ldmatrix.sync.aligned.m8n8.x4.shared.b16 {%0,%1,%2,%3}, [%4];" \
                 : "=r"((r)[0]), "=r"((r)[1]), "=r"((r)[2]), "=r"((r)[3]) \
                 : "r"(addr))

__device__ __forceinline__ void cpa16(uint32_t saddr, const void* gptr) {
    asm volatile("cp.async.cg.shared.global [%0], [%1], 16;\n" :: "r"(saddr), "l"(gptr));
}
__device__ __forceinline__ void cpa_commit() {
    asm volatile("cp.async.commit_group;\n" ::: "memory");
}
__device__ __forceinline__ void cpa_wait1() {
    asm volatile("cp.async.wait_group 1;\n" ::: "memory");
}

// ============================================================================
// weight convert + transpose core: src f32 [K][N] tile -> dst fp16 [N][K]
// ============================================================================
__device__ __forceinline__ void cvtT_tile(const float* __restrict__ src,
                                          __half* __restrict__ dst,
                                          int k0, int n0) {
    __shared__ float sm[64][33];
    const int tid = threadIdx.x;
    const int tx = tid & 31, ty = tid >> 5;

#pragma unroll
    for (int i = 0; i < 8; i++) {
        int ky = ty + i * 8;
        sm[ky][tx] = src[(size_t)(k0 + ky) * 2048 + n0 + tx];
    }
    __syncthreads();

    const int seg = tid & 15;
    const int nyb = tid >> 4;
#pragma unroll
    for (int rep = 0; rep < 2; rep++) {
        int ny = nyb + rep * 16;
        __half2 h0 = __floats2half2_rn(sm[seg * 4 + 0][ny], sm[seg * 4 + 1][ny]);
        __half2 h1 = __floats2half2_rn(sm[seg * 4 + 2][ny], sm[seg * 4 + 3][ny]);
        uint2 pk = { *(uint32_t*)&h0, *(uint32_t*)&h1 };
        *(uint2*)(dst + (size_t)(n0 + ny) * 2048 + k0 + seg * 4) = pk;
    }
}

// shared-expert GEMM1 weights only: z=0 -> Ws1, z=1 -> Wsg  (tiny, critical path)
__global__ void __launch_bounds__(256) cvtT_s1(
        const float* __restrict__ Ws1, const float* __restrict__ Wsg,
        __half* __restrict__ ws1h, __half* __restrict__ wsgh) {
    const float* src = (blockIdx.z == 0) ? Ws1 : Wsg;
    __half* dst      = (blockIdx.z == 0) ? ws1h : wsgh;
    cvtT_tile(src, dst, blockIdx.x * 64, blockIdx.y * 32);
}

// routed GEMM1 weights: z<7 -> W1[z], z<14 -> Wg[z-7]
__global__ void __launch_bounds__(256) cvtT_r1(
        const float* __restrict__ W1, const float* __restrict__ Wg,
        __half* __restrict__ w1h, __half* __restrict__ wgh) {
    const int z = blockIdx.z;
    const float* src;
    __half* dst;
    if (z < 7) { src = W1 + (size_t)z * SELEMS;       dst = w1h + (size_t)z * SELEMS; }
    else       { src = Wg + (size_t)(z - 7) * SELEMS; dst = wgh + (size_t)(z - 7) * SELEMS; }
    cvtT_tile(src, dst, blockIdx.x * 64, blockIdx.y * 32);
}

// GEMM2 weights: z<7 -> W2[z], 7 -> Ws2
__global__ void __launch_bounds__(256) cvtT_g2(
        const float* __restrict__ W2, const float* __restrict__ Ws2,
        __half* __restrict__ w2h, __half* __restrict__ ws2h) {
    const int z = blockIdx.z;
    const float* src;
    __half* dst;
    if (z < 7) { src = W2 + (size_t)z * SELEMS; dst = w2h + (size_t)z * SELEMS; }
    else       { src = Ws2; dst = ws2h; }
    cvtT_tile(src, dst, blockIdx.x * 64, blockIdx.y * 32);
}

// ============================================================================
// zero routing counters
// ============================================================================
__global__ void zero_cnt() {
    if (threadIdx.x < NEXP) g_cnt[threadIdx.x] = 0;
}

// ============================================================================
// FUSED gate + x-convert: one block per token.
// ============================================================================
__global__ void __launch_bounds__(256) gate_cvt(const float* __restrict__ x,
                                                const float* __restrict__ gw,
                                                const float* __restrict__ gb,
                                                const float* __restrict__ biases) {
    const int t = blockIdx.x;
    const float4* xr = (const float4*)(x + (size_t)t * D_DIM);
    __half2* xo = (__half2*)(g_xh + (size_t)t * D_DIM);

    float p[NEXP];
#pragma unroll
    for (int e = 0; e < NEXP; e++) p[e] = 0.f;

#pragma unroll
    for (int i = 0; i < 2; i++) {
        int idx = threadIdx.x + i * 256;
        float4 v = xr[idx];
        xo[idx * 2]     = __floats2half2_rn(v.x, v.y);
        xo[idx * 2 + 1] = __floats2half2_rn(v.z, v.w);
        const float* g0 = gw + (size_t)(idx * 4) * NEXP;
#pragma unroll
        for (int e = 0; e < NEXP; e++)
            p[e] += v.x * g0[e] + v.y * g0[NEXP + e] + v.z * g0[2 * NEXP + e]
                  + v.w * g0[3 * NEXP + e];
    }

#pragma unroll
    for (int off = 16; off > 0; off >>= 1) {
#pragma unroll
        for (int e = 0; e < NEXP; e++)
            p[e] += __shfl_xor_sync(0xffffffffu, p[e], off);
    }

    __shared__ float sm[8][NEXP];
    const int wid = threadIdx.x >> 5, lane = threadIdx.x & 31;
    if (lane == 0) {
#pragma unroll
        for (int e = 0; e < NEXP; e++) sm[wid][e] = p[e];
    }
    __syncthreads();

    if (threadIdx.x == 0) {
        float logit[NEXP];
#pragma unroll
        for (int e = 0; e < NEXP; e++) {
            float s = gb[e];
#pragma unroll
            for (int w = 0; w < 8; w++) s += sm[w][e];
            logit[e] = s;
        }

        float mx = logit[0];
#pragma unroll
        for (int e = 1; e < NEXP; e++) mx = fmaxf(mx, logit[e]);
        float pr[NEXP], den = 0.f;
#pragma unroll
        for (int e = 0; e < NEXP; e++) { pr[e] = __expf(logit[e] - mx); den += pr[e]; }
#pragma unroll
        for (int e = 0; e < NEXP; e++) pr[e] /= den;

        float bi[NEXP];
#pragma unroll
        for (int e = 0; e < NEXP; e++) bi[e] = pr[e] + biases[e];

        bool used[NEXP] = {false, false, false, false, false, false, false};
        int sel[TOPK];
#pragma unroll
        for (int k = 0; k < TOPK; k++) {
            int best = -1; float bv = -1e30f;
#pragma unroll
            for (int e = 0; e < NEXP; e++)
                if (!used[e] && bi[e] > bv) { bv = bi[e]; best = e; }
            used[best] = true; sel[k] = best;
        }
        float ws = pr[sel[0]] + pr[sel[1]] + pr[sel[2]];

#pragma unroll
        for (int k = 0; k < TOPK; k++) {
            int e = sel[k];
            float w = pr[e] / ws;
            int pos = atomicAdd(&g_cnt[e], 1);
            g_idx[e][pos] = t;
            g_te[t][k] = e;
            g_tp[t][k] = pos;
            g_tw[t][k] = w;
        }
    }
}

// ============================================================================
// GEMM1 (fp16): act[z] = silu(Xg @ W1[z]) * (Xg @ Wg[z]);  z = zbase + blockIdx.z
// ============================================================================
__global__ void __launch_bounds__(NTHREADS, 1)
gemm1_all(int zbase) {
    extern __shared__ __half smemh[];
    const uint32_t sbase = (uint32_t)__cvta_generic_to_shared(smemh);
    const int z = zbase + blockIdx.z;

    const __half *B1p, *Bgp;
    int cnt;
    const int* idxp;
    if (z < NEXP) {
        B1p = g_w1h + (size_t)z * D_DIM * H_DIM;
        Bgp = g_wgh + (size_t)z * D_DIM * H_DIM;
        cnt = g_cnt[z];
        idxp = g_idx[z];
    } else {
        B1p = g_ws1h; Bgp = g_wsgh; cnt = T_TOK; idxp = nullptr;
    }

    const int m0 = blockIdx.x * BM;
    if (m0 >= cnt) return;
    const int n0 = blockIdx.y * BN;
    const int tid = threadIdx.x;

    int trow[2];
#pragma unroll
    for (int i = 0; i < 2; i++) {
        int r = m0 + ((tid + i * NTHREADS) >> 3);
        int t;
        if (idxp) t = (r < cnt) ? idxp[r] : 0;
        else      t = r;
        trow[i] = t;
    }

    auto load_stage = [&](int s, int k0) {
        const uint32_t xb = sbase + s * STAGE1B;
        const uint32_t b1 = xb + TILE_B;
        const uint32_t bg = b1 + TILE_B;
#pragma unroll
        for (int i = 0; i < 2; i++) {
            int c = tid + i * NTHREADS;
            int r = c >> 3, j = c & 7;
            cpa16(xb + (r * XSTRH + j * 8) * 2,
                  g_xh + (size_t)trow[i] * D_DIM + k0 + j * 8);
        }
#pragma unroll
        for (int i = 0; i < 2; i++) {
            int c = tid + i * NTHREADS;
            int r = c >> 3, j = c & 7;
            cpa16(b1 + (r * XSTRH + j * 8) * 2,
                  B1p + (size_t)(n0 + r) * D_DIM + k0 + j * 8);
            cpa16(bg + (r * XSTRH + j * 8) * 2,
                  Bgp + (size_t)(n0 + r) * D_DIM + k0 + j * 8);
        }
        cpa_commit();
    };

    float acc1[2][4][4];
    float accg[2][4][4];
#pragma unroll
    for (int i = 0; i < 2; i++)
#pragma unroll
        for (int j = 0; j < 4; j++)
#pragma unroll
            for (int r = 0; r < 4; r++) { acc1[i][j][r] = 0.f; accg[i][j][r] = 0.f; }

    const int wid = tid >> 5, lane = tid & 31;
    const int wm = (wid & 3) * 32, wn = (wid >> 2) * 32;
    const int qr = lane >> 2, qk = lane & 3;

    const int l8 = lane & 7;
    uint32_t a_off[2], b_off[2];
#pragma unroll
    for (int mf = 0; mf < 2; mf++)
        a_off[mf] = ((wm + mf * 16 + l8 + ((lane >> 3) & 1) * 8) * XSTRH
                     + ((lane >> 4) & 1) * 8) * 2;
#pragma unroll
    for (int p = 0; p < 2; p++)
        b_off[p] = ((wn + p * 16 + l8 + ((lane >> 4) & 1) * 8) * XSTRH
                    + ((lane >> 3) & 1) * 8) * 2;

    load_stage(0, 0);
    load_stage(1, BKH);
    for (int it = 0; it < NIT; ++it) {
        cpa_wait1();
        __syncthreads();
        if (it + NS1 - 1 < NIT) load_stage((it + NS1 - 1) % NS1, (it + NS1 - 1) * BKH);

        const uint32_t xb = sbase + (it % NS1) * STAGE1B;
        const uint32_t b1 = xb + TILE_B;
        const uint32_t bg = b1 + TILE_B;

#pragma unroll
        for (int kk = 0; kk < 4; kk++) {
            const int kb = kk * 32;
            uint32_t a[2][4];
#pragma unroll
            for (int mf = 0; mf < 2; mf++) LDSM4(a[mf], xb + a_off[mf] + kb);
#pragma unroll
            for (int p = 0; p < 2; p++) {
                uint32_t b[4], g[4];
                LDSM4(b, b1 + b_off[p] + kb);
                LDSM4(g, bg + b_off[p] + kb);
#pragma unroll
                for (int mf = 0; mf < 2; mf++) {
                    mma_f16(acc1[mf][2 * p],     a[mf], b[0], b[1]);
                    mma_f16(acc1[mf][2 * p + 1], a[mf], b[2], b[3]);
                    mma_f16(accg[mf][2 * p],     a[mf], g[0], g[1]);
                    mma_f16(accg[mf][2 * p + 1], a[mf], g[2], g[3]);
                }
            }
        }
    }

    __half* actp = g_acth[z];
#pragma unroll
    for (int mf = 0; mf < 2; mf++) {
        int r0 = m0 + wm + mf * 16 + qr;
        int r1 = r0 + 8;
#pragma unroll
        for (int nf = 0; nf < 4; nf++) {
            int cl = n0 + wn + nf * 8 + qk * 2;
            __half2 h0 = __floats2half2_rn(silu_f(acc1[mf][nf][0]) * accg[mf][nf][0],
                                           silu_f(acc1[mf][nf][1]) * accg[mf][nf][1]);
            __half2 h1 = __floats2half2_rn(silu_f(acc1[mf][nf][2]) * accg[mf][nf][2],
                                           silu_f(acc1[mf][nf][3]) * accg[mf][nf][3]);
            *(__half2*)(actp + (size_t)r0 * H_DIM + cl) = h0;
            *(__half2*)(actp + (size_t)r1 * H_DIM + cl) = h1;
        }
    }
}

// ============================================================================
// GEMM2 mainloop shared between routed and fused-shared variants.
// Computes acc[4][4][4] for block (m0, n0) of act[z] @ W2-like matrix Bp.
// ============================================================================
__device__ __forceinline__ void gemm2_main(const __half* __restrict__ Ap,
                                           const __half* __restrict__ Bp,
                                           int m0, int n0, int tid,
                                           uint32_t sbase, float acc[4][4][4]) {
    auto load_stage = [&](int s, int k0) {
        const uint32_t ab = sbase + s * STAGE2B;
        const uint32_t bb = ab + TILE_A2B;
#pragma unroll
        for (int i = 0; i < 4; i++) {
            int c = tid + i * NTHREADS;
            int r = c >> 3, j = c & 7;
            cpa16(ab + (r * XSTRH + j * 8) * 2,
                  Ap + (size_t)(m0 + r) * H_DIM + k0 + j * 8);
        }
#pragma unroll
        for (int i = 0; i < 2; i++) {
            int c = tid + i * NTHREADS;
            int r = c >> 3, j = c & 7;
            cpa16(bb + (r * XSTRH + j * 8) * 2,
                  Bp + (size_t)(n0 + r) * H_DIM + k0 + j * 8);
        }
        cpa_commit();
    };

#pragma unroll
    for (int i = 0; i < 4; i++)
#pragma unroll
        for (int j = 0; j < 4; j++)
#pragma unroll
            for (int r = 0; r < 4; r++) acc[i][j][r] = 0.f;

    const int wid = tid >> 5, lane = tid & 31;
    const int wm = (wid & 3) * 64, wn = (wid >> 2) * 32;
    const int l8 = lane & 7;

    uint32_t a_off[4], b_off[2];
#pragma unroll
    for (int mf = 0; mf < 4; mf++)
        a_off[mf] = ((wm + mf * 16 + l8 + ((lane >> 3) & 1) * 8) * XSTRH
                     + ((lane >> 4) & 1) * 8) * 2;
#pragma unroll
    for (int p = 0; p < 2; p++)
        b_off[p] = ((wn + p * 16 + l8 + ((lane >> 4) & 1) * 8) * XSTRH
                    + ((lane >> 3) & 1) * 8) * 2;

    load_stage(0, 0);
    load_stage(1, BKH);
    for (int it = 0; it < NIT; ++it) {
        cpa_wait1();
        __syncthreads();
        if (it + NS2 - 1 < NIT) load_stage((it + NS2 - 1) % NS2, (it + NS2 - 1) * BKH);

        const uint32_t ab = sbase + (it % NS2) * STAGE2B;
        const uint32_t bb = ab + TILE_A2B;

#pragma unroll
        for (int kk = 0; kk < 4; kk++) {
            const int kb = kk * 32;
            uint32_t a[4][4];
#pragma unroll
            for (int mf = 0; mf < 4; mf++) LDSM4(a[mf], ab + a_off[mf] + kb);
#pragma unroll
            for (int p = 0; p < 2; p++) {
                uint32_t b[4];
                LDSM4(b, bb + b_off[p] + kb);
#pragma unroll
                for (int mf = 0; mf < 4; mf++) {
                    mma_f16(acc[mf][2 * p],     a[mf], b[0], b[1]);
                    mma_f16(acc[mf][2 * p + 1], a[mf], b[2], b[3]);
                }
            }
        }
    }
}

// ============================================================================
// GEMM2 routed (z = 0..6): y[z] = act[z] @ W2[z]  -> g_y fp16
// ============================================================================
__global__ void __launch_bounds__(NTHREADS, 1)
gemm2_routed() {
    extern __shared__ __half smemh[];
    const uint32_t sbase = (uint32_t)__cvta_generic_to_shared(smemh);
    const int z = blockIdx.z;
    const int cnt = g_cnt[z];
    const int m0 = blockIdx.x * BM2;
    if (m0 >= cnt) return;
    const int n0 = blockIdx.y * BN;
    const int tid = threadIdx.x;

    float acc[4][4][4];
    gemm2_main(g_acth[z], g_w2h + (size_t)z * SELEMS, m0, n0, tid, sbase, acc);

    const int wid = tid >> 5, lane = tid & 31;
    const int wm = (wid & 3) * 64, wn = (wid >> 2) * 32;
    const int qr = lane >> 2, qk = lane & 3;
    __half* yp = g_y[z];

#pragma unroll
    for (int mf = 0; mf < 4; mf++) {
        int r0 = m0 + wm + mf * 16 + qr;
        int r1 = r0 + 8;
#pragma unroll
        for (int nf = 0; nf < 4; nf++) {
            int cl = n0 + wn + nf * 8 + qk * 2;
            if (r0 < cnt)
                *(__half2*)(yp + (size_t)r0 * D_DIM + cl) =
                    __floats2half2_rn(acc[mf][nf][0], acc[mf][nf][1]);
            if (r1 < cnt)
                *(__half2*)(yp + (size_t)r1 * D_DIM + cl) =
                    __floats2half2_rn(acc[mf][nf][2], acc[mf][nf][3]);
        }
    }
}

// ============================================================================
// GEMM2 shared + FUSED combine: out[t] = act_s[t] @ Ws2 + sum_k w_k * y[e_k][pos_k]
// Rows of the shared slice are token ids; epilogue gathers routed y directly.
// ============================================================================
__global__ void __launch_bounds__(NTHREADS, 1)
gemm2_shared_fused(float* __restrict__ out) {
    extern __shared__ __half smemh[];
    const uint32_t sbase = (uint32_t)__cvta_generic_to_shared(smemh);
    const int m0 = blockIdx.x * BM2;
    const int n0 = blockIdx.y * BN;
    const int tid = threadIdx.x;

    float acc[4][4][4];
    gemm2_main(g_acth[NEXP], g_ws2h, m0, n0, tid, sbase, acc);

    const int wid = tid >> 5, lane = tid & 31;
    const int wm = (wid & 3) * 64, wn = (wid >> 2) * 32;
    const int qr = lane >> 2, qk = lane & 3;

#pragma unroll
    for (int mf = 0; mf < 4; mf++) {
        int rows[2] = { m0 + wm + mf * 16 + qr, m0 + wm + mf * 16 + qr + 8 };
        // per-row routing data (rows are token ids for the shared slice)
        const __half* yb[2][TOPK];
        float wv[2][TOPK];
#pragma unroll
        for (int h = 0; h < 2; h++) {
            int t = rows[h];
#pragma unroll
            for (int k = 0; k < TOPK; k++) {
                int e = g_te[t][k];
                yb[h][k] = g_y[e] + (size_t)g_tp[t][k] * D_DIM;
                wv[h][k] = g_tw[t][k];
            }
        }
#pragma unroll
        for (int nf = 0; nf < 4; nf++) {
            int cl = n0 + wn + nf * 8 + qk * 2;
            float2 v0 = { acc[mf][nf][0], acc[mf][nf][1] };
            float2 v1 = { acc[mf][nf][2], acc[mf][nf][3] };
#pragma unroll
            for (int k = 0; k < TOPK; k++) {
                float2 f0 = __half22float2(*(const __half2*)(yb[0][k] + cl));
                float2 f1 = __half22float2(*(const __half2*)(yb[1][k] + cl));
                v0.x += wv[0][k] * f0.x; v0.y += wv[0][k] * f0.y;
                v1.x += wv[1][k] * f1.x; v1.y += wv[1][k] * f1.y;
            }
            *(float2*)(out + (size_t)rows[0] * D_DIM + cl) = v0;
            *(float2*)(out + (size_t)rows[1] * D_DIM + cl) = v1;
        }
    }
}

// ============================================================================
// launcher — pipelined DAG (R13) + fused combine:
//   s2: zero -> gate_cvt
//   s1: cvtT_r1 -> cvtT_g2
//   main: cvtT_s1 -> [gate] -> gemm1(shared) -> [r1] -> gemm1(routed)
//         -> [g2] -> gemm2_routed -> gemm2_shared_fused
// ============================================================================
extern "C" void kernel_launch(void* const* d_in, const int* in_sizes, int n_in,
                              void* d_out, int out_size) {
    const float* x    = (const float*)d_in[0];
    const float* W1   = (const float*)d_in[1];
    const float* Wg   = (const float*)d_in[2];
    const float* W2   = (const float*)d_in[3];
    const float* Ws1  = (const float*)d_in[4];
    const float* Wsg  = (const float*)d_in[5];
    const float* Ws2  = (const float*)d_in[6];
    const float* gw   = (const float*)d_in[7];
    const float* gb   = (const float*)d_in[8];
    const float* bias = (const float*)d_in[9];
    float* out = (float*)d_out;
    (void)in_sizes; (void)n_in; (void)out_size;

    cudaFuncSetAttribute(gemm1_all, cudaFuncAttributeMaxDynamicSharedMemorySize, SMEM1_BYTES);
    cudaFuncSetAttribute(gemm2_routed, cudaFuncAttributeMaxDynamicSharedMemorySize, SMEM2_BYTES);
    cudaFuncSetAttribute(gemm2_shared_fused, cudaFuncAttributeMaxDynamicSharedMemorySize, SMEM2_BYTES);

    __half *w1h, *wgh, *w2h, *ws1h, *wsgh, *ws2h;
    cudaGetSymbolAddress((void**)&w1h,  g_w1h);
    cudaGetSymbolAddress((void**)&wgh,  g_wgh);
    cudaGetSymbolAddress((void**)&w2h,  g_w2h);
    cudaGetSymbolAddress((void**)&ws1h, g_ws1h);
    cudaGetSymbolAddress((void**)&wsgh, g_wsgh);
    cudaGetSymbolAddress((void**)&ws2h, g_ws2h);

    static cudaStream_t s1 = nullptr, s2 = nullptr;
    static cudaEvent_t e0 = nullptr, eR1 = nullptr, eG2 = nullptr, eGate = nullptr;
    if (s1 == nullptr) {
        cudaStreamCreateWithFlags(&s1, cudaStreamNonBlocking);
        cudaStreamCreateWithFlags(&s2, cudaStreamNonBlocking);
        cudaEventCreateWithFlags(&e0,    cudaEventDisableTiming);
        cudaEventCreateWithFlags(&eR1,   cudaEventDisableTiming);
        cudaEventCreateWithFlags(&eG2,   cudaEventDisableTiming);
        cudaEventCreateWithFlags(&eGate, cudaEventDisableTiming);
    }

    // fork
    cudaEventRecord(e0, 0);

    // s2: routing + x convert
    cudaStreamWaitEvent(s2, e0, 0);
    zero_cnt<<<1, 32, 0, s2>>>();
    gate_cvt<<<T_TOK, 256, 0, s2>>>(x, gw, gb, bias);
    cudaEventRecord(eGate, s2);

    // s1: routed gemm1 weights, then gemm2 weights
    cudaStreamWaitEvent(s1, e0, 0);
    cvtT_r1<<<dim3(32, 64, 14), 256, 0, s1>>>(W1, Wg, w1h, wgh);
    cudaEventRecord(eR1, s1);
    cvtT_g2<<<dim3(32, 64, 8), 256, 0, s1>>>(W2, Ws2, w2h, ws2h);
    cudaEventRecord(eG2, s1);

    // main: shared-expert weights, then shared gemm1 when x is ready
    cvtT_s1<<<dim3(32, 64, 2), 256>>>(Ws1, Wsg, ws1h, wsgh);
    cudaStreamWaitEvent(0, eGate, 0);
    gemm1_all<<<dim3(T_TOK / BM, H_DIM / BN, 1), NTHREADS, SMEM1_BYTES>>>(NEXP); // z = 7

    // routed gemm1
    cudaStreamWaitEvent(0, eR1, 0);
    gemm1_all<<<dim3(T_TOK / BM, H_DIM / BN, NEXP), NTHREADS, SMEM1_BYTES>>>(0); // z = 0..6

    // gemm2: routed first, then shared fused with combine
    cudaStreamWaitEvent(0, eG2, 0);
    gemm2_routed<<<dim3(T_TOK / BM2, D_DIM / BN, NEXP), NTHREADS, SMEM2_BYTES>>>();
    gemm2_shared_fused<<<dim3(T_TOK / BM2, D_DIM / BN, 1), NTHREADS, SMEM2_BYTES>>>(out);
}

// round 15
// speedup vs baseline: 1.0294x; 1.0294x over previous
#include <cuda_runtime.h>
#include <cuda_fp16.h>
#include <cstdint>

// ---------------- problem constants ----------------
#define T_TOK 8192
#define D_DIM 2048
#define H_DIM 2048
#define NEXP  7
#define TOPK  3

// ---------------- tiling ----------------
#define BM 128
#define BN 128
#define BM2 256                // gemm2 M-tile
#define BKH 64                 // K-chunk in halfs (128B per row)
#define NTHREADS 512
#define XSTRH 72               // halfs per smem row (padded; conflict-free)
#define NIT (D_DIM / BKH)      // 32 k-iterations

#define TILE_B (128 * XSTRH * 2)        // bytes per 128-row tile = 18432
#define TILE_A2B (256 * XSTRH * 2)      // bytes per 256-row tile = 36864
#define STAGE1B (3 * TILE_B)            // gemm1 stage (A + B1 + Bg) = 55296
#define STAGE2B (TILE_A2B + TILE_B)     // gemm2 stage (A256 + B128) = 55296
#define NS1 3
#define NS2 3
#define SMEM1_BYTES (NS1 * STAGE1B)     // 165888
#define SMEM2_BYTES (NS2 * STAGE2B)     // 165888

#define WELEMS ((size_t)NEXP * D_DIM * H_DIM)
#define SELEMS ((size_t)D_DIM * H_DIM)
#define XELEMS ((size_t)T_TOK * D_DIM)

// ---------------- device scratch (no allocations allowed) ----------------
__device__ int   g_cnt[NEXP];
__device__ __align__(16) int   g_idx[NEXP][T_TOK];
__device__ int   g_te[T_TOK][TOPK];
__device__ int   g_tp[T_TOK][TOPK];
__device__ float g_tw[T_TOK][TOPK];

__device__ __align__(16) __half g_acth[8][(size_t)T_TOK * H_DIM];   // fp16 SwiGLU acts
__device__ __align__(16) __half g_y[NEXP][(size_t)T_TOK * D_DIM];   // staged routed outputs (fp16)
__device__ __align__(16) __half g_ys[(size_t)T_TOK * D_DIM];        // staged shared output (fp16)

// fp16 operands: weights TRANSPOSED to [n][k]; x row-major [m][k]
__device__ __align__(16) __half g_w1h[WELEMS];
__device__ __align__(16) __half g_wgh[WELEMS];
__device__ __align__(16) __half g_w2h[WELEMS];
__device__ __align__(16) __half g_ws1h[SELEMS];
__device__ __align__(16) __half g_wsgh[SELEMS];
__device__ __align__(16) __half g_ws2h[SELEMS];
__device__ __align__(16) __half g_xh[XELEMS];

// ---------------- helpers ----------------
__device__ __forceinline__ float silu_f(float z) {
    return z / (1.0f + __expf(-z));
}

__device__ __forceinline__ void mma_f16(float c[4], const uint32_t a[4],
                                        const uint32_t b0, const uint32_t b1) {
    asm volatile(
        "mma.sync.aligned.m16n8k16.row.col.f32.f16.f16.f32 "
        "{%0,%1,%2,%3}, {%4,%5,%6,%7}, {%8,%9}, {%0,%1,%2,%3};\n"
        : "+f"(c[0]), "+f"(c[1]), "+f"(c[2]), "+f"(c[3])
        : "r"(a[0]), "r"(a[1]), "r"(a[2]), "r"(a[3]),
          "r"(b0), "r"(b1));
}

#define LDSM4(r, addr) \
    asm volatile("ldmatrix.sync.aligned.m8n8.x4.shared.b16 {%0,%1,%2,%3}, [%4];" \
                 : "=r"((r)[0]), "=r"((r)[1]), "=r"((r)[2]), "=r"((r)[3]) \
                 : "r"(addr))

__device__ __forceinline__ void cpa16(uint32_t saddr, const void* gptr) {
    asm volatile("cp.async.cg.shared.global [%0], [%1], 16;\n" :: "r"(saddr), "l"(gptr));
}
__device__ __forceinline__ void cpa_commit() {
    asm volatile("cp.async.commit_group;\n" ::: "memory");
}
__device__ __forceinline__ void cpa_wait1() {
    asm volatile("cp.async.wait_group 1;\n" ::: "memory");
}

// ============================================================================
// weight convert + transpose core: src f32 [K][N] tile -> dst fp16 [N][K]
// ============================================================================
__device__ __forceinline__ void cvtT_tile(const float* __restrict__ src,
                                          __half* __restrict__ dst,
                                          int k0, int n0) {
    __shared__ float sm[64][33];
    const int tid = threadIdx.x;
    const int tx = tid & 31, ty = tid >> 5;

#pragma unroll
    for (int i = 0; i < 8; i++) {
        int ky = ty + i * 8;
        sm[ky][tx] = src[(size_t)(k0 + ky) * 2048 + n0 + tx];
    }
    __syncthreads();

    const int seg = tid & 15;
    const int nyb = tid >> 4;
#pragma unroll
    for (int rep = 0; rep < 2; rep++) {
        int ny = nyb + rep * 16;
        __half2 h0 = __floats2half2_rn(sm[seg * 4 + 0][ny], sm[seg * 4 + 1][ny]);
        __half2 h1 = __floats2half2_rn(sm[seg * 4 + 2][ny], sm[seg * 4 + 3][ny]);
        uint2 pk = { *(uint32_t*)&h0, *(uint32_t*)&h1 };
        *(uint2*)(dst + (size_t)(n0 + ny) * 2048 + k0 + seg * 4) = pk;
    }
}

// shared-expert GEMM1 weights only: z=0 -> Ws1, z=1 -> Wsg  (tiny, critical path)
__global__ void __launch_bounds__(256) cvtT_s1(
        const float* __restrict__ Ws1, const float* __restrict__ Wsg,
        __half* __restrict__ ws1h, __half* __restrict__ wsgh) {
    const float* src = (blockIdx.z == 0) ? Ws1 : Wsg;
    __half* dst      = (blockIdx.z == 0) ? ws1h : wsgh;
    cvtT_tile(src, dst, blockIdx.x * 64, blockIdx.y * 32);
}

// routed GEMM1 weights: z<7 -> W1[z], z<14 -> Wg[z-7]
__global__ void __launch_bounds__(256) cvtT_r1(
        const float* __restrict__ W1, const float* __restrict__ Wg,
        __half* __restrict__ w1h, __half* __restrict__ wgh) {
    const int z = blockIdx.z;
    const float* src;
    __half* dst;
    if (z < 7) { src = W1 + (size_t)z * SELEMS;       dst = w1h + (size_t)z * SELEMS; }
    else       { src = Wg + (size_t)(z - 7) * SELEMS; dst = wgh + (size_t)(z - 7) * SELEMS; }
    cvtT_tile(src, dst, blockIdx.x * 64, blockIdx.y * 32);
}

// GEMM2 weights: z<7 -> W2[z], 7 -> Ws2
__global__ void __launch_bounds__(256) cvtT_g2(
        const float* __restrict__ W2, const float* __restrict__ Ws2,
        __half* __restrict__ w2h, __half* __restrict__ ws2h) {
    const int z = blockIdx.z;
    const float* src;
    __half* dst;
    if (z < 7) { src = W2 + (size_t)z * SELEMS; dst = w2h + (size_t)z * SELEMS; }
    else       { src = Ws2; dst = ws2h; }
    cvtT_tile(src, dst, blockIdx.x * 64, blockIdx.y * 32);
}

// ============================================================================
// zero routing counters
// ============================================================================
__global__ void zero_cnt() {
    if (threadIdx.x < NEXP) g_cnt[threadIdx.x] = 0;
}

// ============================================================================
// FUSED gate + x-convert: one block per token.
// ============================================================================
__global__ void __launch_bounds__(256) gate_cvt(const float* __restrict__ x,
                                                const float* __restrict__ gw,
                                                const float* __restrict__ gb,
                                                const float* __restrict__ biases) {
    const int t = blockIdx.x;
    const float4* xr = (const float4*)(x + (size_t)t * D_DIM);
    __half2* xo = (__half2*)(g_xh + (size_t)t * D_DIM);

    float p[NEXP];
#pragma unroll
    for (int e = 0; e < NEXP; e++) p[e] = 0.f;

#pragma unroll
    for (int i = 0; i < 2; i++) {
        int idx = threadIdx.x + i * 256;
        float4 v = xr[idx];
        xo[idx * 2]     = __floats2half2_rn(v.x, v.y);
        xo[idx * 2 + 1] = __floats2half2_rn(v.z, v.w);
        const float* g0 = gw + (size_t)(idx * 4) * NEXP;
#pragma unroll
        for (int e = 0; e < NEXP; e++)
            p[e] += v.x * g0[e] + v.y * g0[NEXP + e] + v.z * g0[2 * NEXP + e]
                  + v.w * g0[3 * NEXP + e];
    }

#pragma unroll
    for (int off = 16; off > 0; off >>= 1) {
#pragma unroll
        for (int e = 0; e < NEXP; e++)
            p[e] += __shfl_xor_sync(0xffffffffu, p[e], off);
    }

    __shared__ float sm[8][NEXP];
    const int wid = threadIdx.x >> 5, lane = threadIdx.x & 31;
    if (lane == 0) {
#pragma unroll
        for (int e = 0; e < NEXP; e++) sm[wid][e] = p[e];
    }
    __syncthreads();

    if (threadIdx.x == 0) {
        float logit[NEXP];
#pragma unroll
        for (int e = 0; e < NEXP; e++) {
            float s = gb[e];
#pragma unroll
            for (int w = 0; w < 8; w++) s += sm[w][e];
            logit[e] = s;
        }

        float mx = logit[0];
#pragma unroll
        for (int e = 1; e < NEXP; e++) mx = fmaxf(mx, logit[e]);
        float pr[NEXP], den = 0.f;
#pragma unroll
        for (int e = 0; e < NEXP; e++) { pr[e] = __expf(logit[e] - mx); den += pr[e]; }
#pragma unroll
        for (int e = 0; e < NEXP; e++) pr[e] /= den;

        float bi[NEXP];
#pragma unroll
        for (int e = 0; e < NEXP; e++) bi[e] = pr[e] + biases[e];

        bool used[NEXP] = {false, false, false, false, false, false, false};
        int sel[TOPK];
#pragma unroll
        for (int k = 0; k < TOPK; k++) {
            int best = -1; float bv = -1e30f;
#pragma unroll
            for (int e = 0; e < NEXP; e++)
                if (!used[e] && bi[e] > bv) { bv = bi[e]; best = e; }
            used[best] = true; sel[k] = best;
        }
        float ws = pr[sel[0]] + pr[sel[1]] + pr[sel[2]];

#pragma unroll
        for (int k = 0; k < TOPK; k++) {
            int e = sel[k];
            float w = pr[e] / ws;
            int pos = atomicAdd(&g_cnt[e], 1);
            g_idx[e][pos] = t;
            g_te[t][k] = e;
            g_tp[t][k] = pos;
            g_tw[t][k] = w;
        }
    }
}

// ============================================================================
// GEMM1 (fp16): act[z] = silu(Xg @ W1[z]) * (Xg @ Wg[z]);  z = zbase + blockIdx.z
// ============================================================================
__global__ void __launch_bounds__(NTHREADS, 1)
gemm1_all(int zbase) {
    extern __shared__ __half smemh[];
    const uint32_t sbase = (uint32_t)__cvta_generic_to_shared(smemh);
    const int z = zbase + blockIdx.z;

    const __half *B1p, *Bgp;
    int cnt;
    const int* idxp;
    if (z < NEXP) {
        B1p = g_w1h + (size_t)z * D_DIM * H_DIM;
        Bgp = g_wgh + (size_t)z * D_DIM * H_DIM;
        cnt = g_cnt[z];
        idxp = g_idx[z];
    } else {
        B1p = g_ws1h; Bgp = g_wsgh; cnt = T_TOK; idxp = nullptr;
    }

    const int m0 = blockIdx.x * BM;
    if (m0 >= cnt) return;
    const int n0 = blockIdx.y * BN;
    const int tid = threadIdx.x;

    int trow[2];
#pragma unroll
    for (int i = 0; i < 2; i++) {
        int r = m0 + ((tid + i * NTHREADS) >> 3);
        int t;
        if (idxp) t = (r < cnt) ? idxp[r] : 0;
        else      t = r;
        trow[i] = t;
    }

    auto load_stage = [&](int s, int k0) {
        const uint32_t xb = sbase + s * STAGE1B;
        const uint32_t b1 = xb + TILE_B;
        const uint32_t bg = b1 + TILE_B;
#pragma unroll
        for (int i = 0; i < 2; i++) {
            int c = tid + i * NTHREADS;
            int r = c >> 3, j = c & 7;
            cpa16(xb + (r * XSTRH + j * 8) * 2,
                  g_xh + (size_t)trow[i] * D_DIM + k0 + j * 8);
        }
#pragma unroll
        for (int i = 0; i < 2; i++) {
            int c = tid + i * NTHREADS;
            int r = c >> 3, j = c & 7;
            cpa16(b1 + (r * XSTRH + j * 8) * 2,
                  B1p + (size_t)(n0 + r) * D_DIM + k0 + j * 8);
            cpa16(bg + (r * XSTRH + j * 8) * 2,
                  Bgp + (size_t)(n0 + r) * D_DIM + k0 + j * 8);
        }
        cpa_commit();
    };

    float acc1[2][4][4];
    float accg[2][4][4];
#pragma unroll
    for (int i = 0; i < 2; i++)
#pragma unroll
        for (int j = 0; j < 4; j++)
#pragma unroll
            for (int r = 0; r < 4; r++) { acc1[i][j][r] = 0.f; accg[i][j][r] = 0.f; }

    const int wid = tid >> 5, lane = tid & 31;
    const int wm = (wid & 3) * 32, wn = (wid >> 2) * 32;
    const int qr = lane >> 2, qk = lane & 3;

    const int l8 = lane & 7;
    uint32_t a_off[2], b_off[2];
#pragma unroll
    for (int mf = 0; mf < 2; mf++)
        a_off[mf] = ((wm + mf * 16 + l8 + ((lane >> 3) & 1) * 8) * XSTRH
                     + ((lane >> 4) & 1) * 8) * 2;
#pragma unroll
    for (int p = 0; p < 2; p++)
        b_off[p] = ((wn + p * 16 + l8 + ((lane >> 4) & 1) * 8) * XSTRH
                    + ((lane >> 3) & 1) * 8) * 2;

    load_stage(0, 0);
    load_stage(1, BKH);
    for (int it = 0; it < NIT; ++it) {
        cpa_wait1();
        __syncthreads();
        if (it + NS1 - 1 < NIT) load_stage((it + NS1 - 1) % NS1, (it + NS1 - 1) * BKH);

        const uint32_t xb = sbase + (it % NS1) * STAGE1B;
        const uint32_t b1 = xb + TILE_B;
        const uint32_t bg = b1 + TILE_B;

#pragma unroll
        for (int kk = 0; kk < 4; kk++) {
            const int kb = kk * 32;
            uint32_t a[2][4];
#pragma unroll
            for (int mf = 0; mf < 2; mf++) LDSM4(a[mf], xb + a_off[mf] + kb);
#pragma unroll
            for (int p = 0; p < 2; p++) {
                uint32_t b[4], g[4];
                LDSM4(b, b1 + b_off[p] + kb);
                LDSM4(g, bg + b_off[p] + kb);
#pragma unroll
                for (int mf = 0; mf < 2; mf++) {
                    mma_f16(acc1[mf][2 * p],     a[mf], b[0], b[1]);
                    mma_f16(acc1[mf][2 * p + 1], a[mf], b[2], b[3]);
                    mma_f16(accg[mf][2 * p],     a[mf], g[0], g[1]);
                    mma_f16(accg[mf][2 * p + 1], a[mf], g[2], g[3]);
                }
            }
        }
    }

    __half* actp = g_acth[z];
#pragma unroll
    for (int mf = 0; mf < 2; mf++) {
        int r0 = m0 + wm + mf * 16 + qr;
        int r1 = r0 + 8;
#pragma unroll
        for (int nf = 0; nf < 4; nf++) {
            int cl = n0 + wn + nf * 8 + qk * 2;
            __half2 h0 = __floats2half2_rn(silu_f(acc1[mf][nf][0]) * accg[mf][nf][0],
                                           silu_f(acc1[mf][nf][1]) * accg[mf][nf][1]);
            __half2 h1 = __floats2half2_rn(silu_f(acc1[mf][nf][2]) * accg[mf][nf][2],
                                           silu_f(acc1[mf][nf][3]) * accg[mf][nf][3]);
            *(__half2*)(actp + (size_t)r0 * H_DIM + cl) = h0;
            *(__half2*)(actp + (size_t)r1 * H_DIM + cl) = h1;
        }
    }
}

// ============================================================================
// GEMM2 (all experts, fp16): y = act[z] @ W2[z]
// z < 7 -> g_y[z] fp16;  z = 7 -> g_ys fp16 (shared, combined later)
// ============================================================================
__global__ void __launch_bounds__(NTHREADS, 1)
gemm2_all() {
    extern __shared__ __half smemh[];
    const uint32_t sbase = (uint32_t)__cvta_generic_to_shared(smemh);
    const int z = blockIdx.z;

    const __half* Bp;
    int cnt;
    if (z < NEXP) { Bp = g_w2h + (size_t)z * H_DIM * D_DIM; cnt = g_cnt[z]; }
    else          { Bp = g_ws2h; cnt = T_TOK; }
    const __half* Ap = g_acth[z];

    const int m0 = blockIdx.x * BM2;
    if (m0 >= cnt) return;
    const int n0 = blockIdx.y * BN;
    const int tid = threadIdx.x;

    auto load_stage = [&](int s, int k0) {
        const uint32_t ab = sbase + s * STAGE2B;
        const uint32_t bb = ab + TILE_A2B;
#pragma unroll
        for (int i = 0; i < 4; i++) {
            int c = tid + i * NTHREADS;
            int r = c >> 3, j = c & 7;
            cpa16(ab + (r * XSTRH + j * 8) * 2,
                  Ap + (size_t)(m0 + r) * H_DIM + k0 + j * 8);
        }
#pragma unroll
        for (int i = 0; i < 2; i++) {
            int c = tid + i * NTHREADS;
            int r = c >> 3, j = c & 7;
            cpa16(bb + (r * XSTRH + j * 8) * 2,
                  Bp + (size_t)(n0 + r) * H_DIM + k0 + j * 8);
        }
        cpa_commit();
    };

    float acc[4][4][4];
#pragma unroll
    for (int i = 0; i < 4; i++)
#pragma unroll
        for (int j = 0; j < 4; j++)
#pragma unroll
            for (int r = 0; r < 4; r++) acc[i][j][r] = 0.f;

    const int wid = tid >> 5, lane = tid & 31;
    const int wm = (wid & 3) * 64, wn = (wid >> 2) * 32;
    const int qr = lane >> 2, qk = lane & 3;

    const int l8 = lane & 7;
    uint32_t a_off[4], b_off[2];
#pragma unroll
    for (int mf = 0; mf < 4; mf++)
        a_off[mf] = ((wm + mf * 16 + l8 + ((lane >> 3) & 1) * 8) * XSTRH
                     + ((lane >> 4) & 1) * 8) * 2;
#pragma unroll
    for (int p = 0; p < 2; p++)
        b_off[p] = ((wn + p * 16 + l8 + ((lane >> 4) & 1) * 8) * XSTRH
                    + ((lane >> 3) & 1) * 8) * 2;

    load_stage(0, 0);
    load_stage(1, BKH);
    for (int it = 0; it < NIT; ++it) {
        cpa_wait1();
        __syncthreads();
        if (it + NS2 - 1 < NIT) load_stage((it + NS2 - 1) % NS2, (it + NS2 - 1) * BKH);

        const uint32_t ab = sbase + (it % NS2) * STAGE2B;
        const uint32_t bb = ab + TILE_A2B;

#pragma unroll
        for (int kk = 0; kk < 4; kk++) {
            const int kb = kk * 32;
            uint32_t a[4][4];
#pragma unroll
            for (int mf = 0; mf < 4; mf++) LDSM4(a[mf], ab + a_off[mf] + kb);
#pragma unroll
            for (int p = 0; p < 2; p++) {
                uint32_t b[4];
                LDSM4(b, bb + b_off[p] + kb);
#pragma unroll
                for (int mf = 0; mf < 4; mf++) {
                    mma_f16(acc[mf][2 * p],     a[mf], b[0], b[1]);
                    mma_f16(acc[mf][2 * p + 1], a[mf], b[2], b[3]);
                }
            }
        }
    }

    __half* yp = (z == NEXP) ? g_ys : g_y[z];
#pragma unroll
    for (int mf = 0; mf < 4; mf++) {
        int r0 = m0 + wm + mf * 16 + qr;
        int r1 = r0 + 8;
#pragma unroll
        for (int nf = 0; nf < 4; nf++) {
            int cl = n0 + wn + nf * 8 + qk * 2;
            if (r0 < cnt)
                *(__half2*)(yp + (size_t)r0 * D_DIM + cl) =
                    __floats2half2_rn(acc[mf][nf][0], acc[mf][nf][1]);
            if (r1 < cnt)
                *(__half2*)(yp + (size_t)r1 * D_DIM + cl) =
                    __floats2half2_rn(acc[mf][nf][2], acc[mf][nf][3]);
        }
    }
}

// ============================================================================
// combine: out[t] = ys[t] + sum_k w_k * y[e_k][pos_k]   (all fp16 in, f32 out)
// ============================================================================
__global__ void __launch_bounds__(256) combine_kernel(float* __restrict__ out) {
    const int t = blockIdx.x;
    const int e0 = g_te[t][0], e1 = g_te[t][1], e2 = g_te[t][2];
    const float w0 = g_tw[t][0], w1 = g_tw[t][1], w2 = g_tw[t][2];
    const uint4* ys = (const uint4*)(g_ys + (size_t)t * D_DIM);
    const uint4* y0 = (const uint4*)(g_y[e0] + (size_t)g_tp[t][0] * D_DIM);
    const uint4* y1 = (const uint4*)(g_y[e1] + (size_t)g_tp[t][1] * D_DIM);
    const uint4* y2 = (const uint4*)(g_y[e2] + (size_t)g_tp[t][2] * D_DIM);
    float4* o = (float4*)(out + (size_t)t * D_DIM);

    const int i = threadIdx.x;          // 256 threads x 8 halfs
    uint4 s = ys[i], a = y0[i], b = y1[i], c = y2[i];
    const __half2* sh = (const __half2*)&s;
    const __half2* ah = (const __half2*)&a;
    const __half2* bh = (const __half2*)&b;
    const __half2* ch = (const __half2*)&c;

    float4 v0, v1;
    float2 f;
    f = __half22float2(sh[0]); v0.x = f.x; v0.y = f.y;
    f = __half22float2(sh[1]); v0.z = f.x; v0.w = f.y;
    f = __half22float2(sh[2]); v1.x = f.x; v1.y = f.y;
    f = __half22float2(sh[3]); v1.z = f.x; v1.w = f.y;

    f = __half22float2(ah[0]); v0.x += w0 * f.x; v0.y += w0 * f.y;
    f = __half22float2(ah[1]); v0.z += w0 * f.x; v0.w += w0 * f.y;
    f = __half22float2(ah[2]); v1.x += w0 * f.x; v1.y += w0 * f.y;
    f = __half22float2(ah[3]); v1.z += w0 * f.x; v1.w += w0 * f.y;

    f = __half22float2(bh[0]); v0.x += w1 * f.x; v0.y += w1 * f.y;
    f = __half22float2(bh[1]); v0.z += w1 * f.x; v0.w += w1 * f.y;
    f = __half22float2(bh[2]); v1.x += w1 * f.x; v1.y += w1 * f.y;
    f = __half22float2(bh[3]); v1.z += w1 * f.x; v1.w += w1 * f.y;

    f = __half22float2(ch[0]); v0.x += w2 * f.x; v0.y += w2 * f.y;
    f = __half22float2(ch[1]); v0.z += w2 * f.x; v0.w += w2 * f.y;
    f = __half22float2(ch[2]); v1.x += w2 * f.x; v1.y += w2 * f.y;
    f = __half22float2(ch[3]); v1.z += w2 * f.x; v1.w += w2 * f.y;

    o[i * 2]     = v0;
    o[i * 2 + 1] = v1;
}

// ============================================================================
// launcher — pipelined DAG (R13 structure):
//   s2: zero -> gate_cvt
//   s1: cvtT_r1 -> cvtT_g2
//   main: cvtT_s1 -> [gate] -> gemm1(shared) -> [r1] -> gemm1(routed)
//         -> [g2] -> gemm2(all 8) -> combine
// ============================================================================
extern "C" void kernel_launch(void* const* d_in, const int* in_sizes, int n_in,
                              void* d_out, int out_size) {
    const float* x    = (const float*)d_in[0];
    const float* W1   = (const float*)d_in[1];
    const float* Wg   = (const float*)d_in[2];
    const float* W2   = (const float*)d_in[3];
    const float* Ws1  = (const float*)d_in[4];
    const float* Wsg  = (const float*)d_in[5];
    const float* Ws2  = (const float*)d_in[6];
    const float* gw   = (const float*)d_in[7];
    const float* gb   = (const float*)d_in[8];
    const float* bias = (const float*)d_in[9];
    float* out = (float*)d_out;
    (void)in_sizes; (void)n_in; (void)out_size;

    cudaFuncSetAttribute(gemm1_all, cudaFuncAttributeMaxDynamicSharedMemorySize, SMEM1_BYTES);
    cudaFuncSetAttribute(gemm2_all, cudaFuncAttributeMaxDynamicSharedMemorySize, SMEM2_BYTES);

    __half *w1h, *wgh, *w2h, *ws1h, *wsgh, *ws2h;
    cudaGetSymbolAddress((void**)&w1h,  g_w1h);
    cudaGetSymbolAddress((void**)&wgh,  g_wgh);
    cudaGetSymbolAddress((void**)&w2h,  g_w2h);
    cudaGetSymbolAddress((void**)&ws1h, g_ws1h);
    cudaGetSymbolAddress((void**)&wsgh, g_wsgh);
    cudaGetSymbolAddress((void**)&ws2h, g_ws2h);

    static cudaStream_t s1 = nullptr, s2 = nullptr;
    static cudaEvent_t e0 = nullptr, eR1 = nullptr, eG2 = nullptr, eGate = nullptr;
    if (s1 == nullptr) {
        cudaStreamCreateWithFlags(&s1, cudaStreamNonBlocking);
        cudaStreamCreateWithFlags(&s2, cudaStreamNonBlocking);
        cudaEventCreateWithFlags(&e0,    cudaEventDisableTiming);
        cudaEventCreateWithFlags(&eR1,   cudaEventDisableTiming);
        cudaEventCreateWithFlags(&eG2,   cudaEventDisableTiming);
        cudaEventCreateWithFlags(&eGate, cudaEventDisableTiming);
    }

    // fork
    cudaEventRecord(e0, 0);

    // s2: routing + x convert
    cudaStreamWaitEvent(s2, e0, 0);
    zero_cnt<<<1, 32, 0, s2>>>();
    gate_cvt<<<T_TOK, 256, 0, s2>>>(x, gw, gb, bias);
    cudaEventRecord(eGate, s2);

    // s1: routed gemm1 weights, then gemm2 weights
    cudaStreamWaitEvent(s1, e0, 0);
    cvtT_r1<<<dim3(32, 64, 14), 256, 0, s1>>>(W1, Wg, w1h, wgh);
    cudaEventRecord(eR1, s1);
    cvtT_g2<<<dim3(32, 64, 8), 256, 0, s1>>>(W2, Ws2, w2h, ws2h);
    cudaEventRecord(eG2, s1);

    // main: shared-expert weights, then shared gemm1 when x is ready
    cvtT_s1<<<dim3(32, 64, 2), 256>>>(Ws1, Wsg, ws1h, wsgh);
    cudaStreamWaitEvent(0, eGate, 0);
    gemm1_all<<<dim3(T_TOK / BM, H_DIM / BN, 1), NTHREADS, SMEM1_BYTES>>>(NEXP); // z = 7

    // routed gemm1
    cudaStreamWaitEvent(0, eR1, 0);
    gemm1_all<<<dim3(T_TOK / BM, H_DIM / BN, NEXP), NTHREADS, SMEM1_BYTES>>>(0); // z = 0..6

    // gemm2 (all 8 slices, one launch) + combine
    cudaStreamWaitEvent(0, eG2, 0);
    gemm2_all<<<dim3(T_TOK / BM2, D_DIM / BN, 8), NTHREADS, SMEM2_BYTES>>>();
    combine_kernel<<<T_TOK, 256>>>(out);
}

// round 16
// speedup vs baseline: 1.0340x; 1.0045x over previous
#include <cuda_runtime.h>
#include <cuda_fp16.h>
#include <cstdint>

// ---------------- problem constants ----------------
#define T_TOK 8192
#define D_DIM 2048
#define H_DIM 2048
#define NEXP  7
#define TOPK  3

// ---------------- tiling ----------------
#define BM 128
#define BN 128
#define BM2 256                // gemm2 M-tile
#define BKH 64                 // K-chunk in halfs (128B per row)
#define NTHREADS 512
#define XSTRH 72               // halfs per smem row (padded; conflict-free)
#define NIT (D_DIM / BKH)      // 32 k-iterations

#define TILE_B (128 * XSTRH * 2)        // bytes per 128-row tile = 18432
#define TILE_A2B (256 * XSTRH * 2)      // bytes per 256-row tile = 36864
#define STAGE1B (3 * TILE_B)            // gemm1 stage (A + B1 + Bg) = 55296
#define STAGE2B (TILE_A2B + TILE_B)     // gemm2 stage (A256 + B128) = 55296
#define NS1 3
#define NS2 3
#define SMEM1_BYTES (NS1 * STAGE1B)     // 165888
#define SMEM2_BYTES (NS2 * STAGE2B)     // 165888

#define WELEMS ((size_t)NEXP * D_DIM * H_DIM)
#define SELEMS ((size_t)D_DIM * H_DIM)
#define XELEMS ((size_t)T_TOK * D_DIM)

// ---------------- device scratch (no allocations allowed) ----------------
__device__ int   g_cnt[NEXP];
__device__ __align__(16) int   g_idx[NEXP][T_TOK];
__device__ int   g_te[T_TOK][TOPK];
__device__ int   g_tp[T_TOK][TOPK];
__device__ float g_tw[T_TOK][TOPK];

__device__ __align__(16) __half g_acth[8][(size_t)T_TOK * H_DIM];   // fp16 SwiGLU acts
__device__ __align__(16) __half g_y[NEXP][(size_t)T_TOK * D_DIM];   // staged routed outputs (fp16)
__device__ __align__(16) __half g_ys[(size_t)T_TOK * D_DIM];        // staged shared output (fp16)

// fp16 operands: weights TRANSPOSED to [n][k]; x row-major [m][k]
__device__ __align__(16) __half g_w1h[WELEMS];
__device__ __align__(16) __half g_wgh[WELEMS];
__device__ __align__(16) __half g_w2h[WELEMS];
__device__ __align__(16) __half g_ws1h[SELEMS];
__device__ __align__(16) __half g_wsgh[SELEMS];
__device__ __align__(16) __half g_ws2h[SELEMS];
__device__ __align__(16) __half g_xh[XELEMS];

// ---------------- helpers ----------------
__device__ __forceinline__ float silu_f(float z) {
    return z / (1.0f + __expf(-z));
}

__device__ __forceinline__ void mma_f16(float c[4], const uint32_t a[4],
                                        const uint32_t b0, const uint32_t b1) {
    asm volatile(
        "mma.sync.aligned.m16n8k16.row.col.f32.f16.f16.f32 "
        "{%0,%1,%2,%3}, {%4,%5,%6,%7}, {%8,%9}, {%0,%1,%2,%3};\n"
        : "+f"(c[0]), "+f"(c[1]), "+f"(c[2]), "+f"(c[3])
        : "r"(a[0]), "r"(a[1]), "r"(a[2]), "r"(a[3]),
          "r"(b0), "r"(b1));
}

#define LDSM4(r, addr) \
    asm volatile("ldmatrix.sync.aligned.m8n8.x4.shared.b16 {%0,%1,%2,%3}, [%4];" \
                 : "=r"((r)[0]), "=r"((r)[1]), "=r"((r)[2]), "=r"((r)[3]) \
                 : "r"(addr))

__device__ __forceinline__ void cpa16(uint32_t saddr, const void* gptr) {
    asm volatile("cp.async.cg.shared.global [%0], [%1], 16;\n" :: "r"(saddr), "l"(gptr));
}
__device__ __forceinline__ void cpa_commit() {
    asm volatile("cp.async.commit_group;\n" ::: "memory");
}
__device__ __forceinline__ void cpa_wait1() {
    asm volatile("cp.async.wait_group 1;\n" ::: "memory");
}

// ============================================================================
// weight convert + transpose core: src f32 [K][N] tile -> dst fp16 [N][K]
// ============================================================================
__device__ __forceinline__ void cvtT_tile(const float* __restrict__ src,
                                          __half* __restrict__ dst,
                                          int k0, int n0) {
    __shared__ float sm[64][33];
    const int tid = threadIdx.x;
    const int tx = tid & 31, ty = tid >> 5;

#pragma unroll
    for (int i = 0; i < 8; i++) {
        int ky = ty + i * 8;
        sm[ky][tx] = src[(size_t)(k0 + ky) * 2048 + n0 + tx];
    }
    __syncthreads();

    const int seg = tid & 15;
    const int nyb = tid >> 4;
#pragma unroll
    for (int rep = 0; rep < 2; rep++) {
        int ny = nyb + rep * 16;
        __half2 h0 = __floats2half2_rn(sm[seg * 4 + 0][ny], sm[seg * 4 + 1][ny]);
        __half2 h1 = __floats2half2_rn(sm[seg * 4 + 2][ny], sm[seg * 4 + 3][ny]);
        uint2 pk = { *(uint32_t*)&h0, *(uint32_t*)&h1 };
        *(uint2*)(dst + (size_t)(n0 + ny) * 2048 + k0 + seg * 4) = pk;
    }
}

// shared-expert GEMM1 weights only: z=0 -> Ws1, z=1 -> Wsg  (tiny, critical path)
__global__ void __launch_bounds__(256) cvtT_s1(
        const float* __restrict__ Ws1, const float* __restrict__ Wsg,
        __half* __restrict__ ws1h, __half* __restrict__ wsgh) {
    const float* src = (blockIdx.z == 0) ? Ws1 : Wsg;
    __half* dst      = (blockIdx.z == 0) ? ws1h : wsgh;
    cvtT_tile(src, dst, blockIdx.x * 64, blockIdx.y * 32);
}

// routed GEMM1 weights: z<7 -> W1[z], z<14 -> Wg[z-7]
__global__ void __launch_bounds__(256) cvtT_r1(
        const float* __restrict__ W1, const float* __restrict__ Wg,
        __half* __restrict__ w1h, __half* __restrict__ wgh) {
    const int z = blockIdx.z;
    const float* src;
    __half* dst;
    if (z < 7) { src = W1 + (size_t)z * SELEMS;       dst = w1h + (size_t)z * SELEMS; }
    else       { src = Wg + (size_t)(z - 7) * SELEMS; dst = wgh + (size_t)(z - 7) * SELEMS; }
    cvtT_tile(src, dst, blockIdx.x * 64, blockIdx.y * 32);
}

// GEMM2 weights: z<7 -> W2[z], 7 -> Ws2
__global__ void __launch_bounds__(256) cvtT_g2(
        const float* __restrict__ W2, const float* __restrict__ Ws2,
        __half* __restrict__ w2h, __half* __restrict__ ws2h) {
    const int z = blockIdx.z;
    const float* src;
    __half* dst;
    if (z < 7) { src = W2 + (size_t)z * SELEMS; dst = w2h + (size_t)z * SELEMS; }
    else       { src = Ws2; dst = ws2h; }
    cvtT_tile(src, dst, blockIdx.x * 64, blockIdx.y * 32);
}

// ============================================================================
// zero routing counters
// ============================================================================
__global__ void zero_cnt() {
    if (threadIdx.x < NEXP) g_cnt[threadIdx.x] = 0;
}

// ============================================================================
// FUSED gate + x-convert: one block per token.
// ============================================================================
__global__ void __launch_bounds__(256) gate_cvt(const float* __restrict__ x,
                                                const float* __restrict__ gw,
                                                const float* __restrict__ gb,
                                                const float* __restrict__ biases) {
    const int t = blockIdx.x;
    const float4* xr = (const float4*)(x + (size_t)t * D_DIM);
    __half2* xo = (__half2*)(g_xh + (size_t)t * D_DIM);

    float p[NEXP];
#pragma unroll
    for (int e = 0; e < NEXP; e++) p[e] = 0.f;

#pragma unroll
    for (int i = 0; i < 2; i++) {
        int idx = threadIdx.x + i * 256;
        float4 v = xr[idx];
        xo[idx * 2]     = __floats2half2_rn(v.x, v.y);
        xo[idx * 2 + 1] = __floats2half2_rn(v.z, v.w);
        const float* g0 = gw + (size_t)(idx * 4) * NEXP;
#pragma unroll
        for (int e = 0; e < NEXP; e++)
            p[e] += v.x * g0[e] + v.y * g0[NEXP + e] + v.z * g0[2 * NEXP + e]
                  + v.w * g0[3 * NEXP + e];
    }

#pragma unroll
    for (int off = 16; off > 0; off >>= 1) {
#pragma unroll
        for (int e = 0; e < NEXP; e++)
            p[e] += __shfl_xor_sync(0xffffffffu, p[e], off);
    }

    __shared__ float sm[8][NEXP];
    const int wid = threadIdx.x >> 5, lane = threadIdx.x & 31;
    if (lane == 0) {
#pragma unroll
        for (int e = 0; e < NEXP; e++) sm[wid][e] = p[e];
    }
    __syncthreads();

    if (threadIdx.x == 0) {
        float logit[NEXP];
#pragma unroll
        for (int e = 0; e < NEXP; e++) {
            float s = gb[e];
#pragma unroll
            for (int w = 0; w < 8; w++) s += sm[w][e];
            logit[e] = s;
        }

        float mx = logit[0];
#pragma unroll
        for (int e = 1; e < NEXP; e++) mx = fmaxf(mx, logit[e]);
        float pr[NEXP], den = 0.f;
#pragma unroll
        for (int e = 0; e < NEXP; e++) { pr[e] = __expf(logit[e] - mx); den += pr[e]; }
#pragma unroll
        for (int e = 0; e < NEXP; e++) pr[e] /= den;

        float bi[NEXP];
#pragma unroll
        for (int e = 0; e < NEXP; e++) bi[e] = pr[e] + biases[e];

        bool used[NEXP] = {false, false, false, false, false, false, false};
        int sel[TOPK];
#pragma unroll
        for (int k = 0; k < TOPK; k++) {
            int best = -1; float bv = -1e30f;
#pragma unroll
            for (int e = 0; e < NEXP; e++)
                if (!used[e] && bi[e] > bv) { bv = bi[e]; best = e; }
            used[best] = true; sel[k] = best;
        }
        float ws = pr[sel[0]] + pr[sel[1]] + pr[sel[2]];

#pragma unroll
        for (int k = 0; k < TOPK; k++) {
            int e = sel[k];
            float w = pr[e] / ws;
            int pos = atomicAdd(&g_cnt[e], 1);
            g_idx[e][pos] = t;
            g_te[t][k] = e;
            g_tp[t][k] = pos;
            g_tw[t][k] = w;
        }
    }
}

// ============================================================================
// GEMM1 (fp16): act[z] = silu(Xg @ W1[z]) * (Xg @ Wg[z]);  z = zbase + blockIdx.z
// ============================================================================
__global__ void __launch_bounds__(NTHREADS, 1)
gemm1_all(int zbase) {
    extern __shared__ __half smemh[];
    const uint32_t sbase = (uint32_t)__cvta_generic_to_shared(smemh);
    const int z = zbase + blockIdx.z;

    const __half *B1p, *Bgp;
    int cnt;
    const int* idxp;
    if (z < NEXP) {
        B1p = g_w1h + (size_t)z * D_DIM * H_DIM;
        Bgp = g_wgh + (size_t)z * D_DIM * H_DIM;
        cnt = g_cnt[z];
        idxp = g_idx[z];
    } else {
        B1p = g_ws1h; Bgp = g_wsgh; cnt = T_TOK; idxp = nullptr;
    }

    const int m0 = blockIdx.x * BM;
    if (m0 >= cnt) return;
    const int n0 = blockIdx.y * BN;
    const int tid = threadIdx.x;

    int trow[2];
#pragma unroll
    for (int i = 0; i < 2; i++) {
        int r = m0 + ((tid + i * NTHREADS) >> 3);
        int t;
        if (idxp) t = (r < cnt) ? idxp[r] : 0;
        else      t = r;
        trow[i] = t;
    }

    auto load_stage = [&](int s, int k0) {
        const uint32_t xb = sbase + s * STAGE1B;
        const uint32_t b1 = xb + TILE_B;
        const uint32_t bg = b1 + TILE_B;
#pragma unroll
        for (int i = 0; i < 2; i++) {
            int c = tid + i * NTHREADS;
            int r = c >> 3, j = c & 7;
            cpa16(xb + (r * XSTRH + j * 8) * 2,
                  g_xh + (size_t)trow[i] * D_DIM + k0 + j * 8);
        }
#pragma unroll
        for (int i = 0; i < 2; i++) {
            int c = tid + i * NTHREADS;
            int r = c >> 3, j = c & 7;
            cpa16(b1 + (r * XSTRH + j * 8) * 2,
                  B1p + (size_t)(n0 + r) * D_DIM + k0 + j * 8);
            cpa16(bg + (r * XSTRH + j * 8) * 2,
                  Bgp + (size_t)(n0 + r) * D_DIM + k0 + j * 8);
        }
        cpa_commit();
    };

    float acc1[2][4][4];
    float accg[2][4][4];
#pragma unroll
    for (int i = 0; i < 2; i++)
#pragma unroll
        for (int j = 0; j < 4; j++)
#pragma unroll
            for (int r = 0; r < 4; r++) { acc1[i][j][r] = 0.f; accg[i][j][r] = 0.f; }

    const int wid = tid >> 5, lane = tid & 31;
    const int wm = (wid & 3) * 32, wn = (wid >> 2) * 32;
    const int qr = lane >> 2, qk = lane & 3;

    const int l8 = lane & 7;
    uint32_t a_off[2], b_off[2];
#pragma unroll
    for (int mf = 0; mf < 2; mf++)
        a_off[mf] = ((wm + mf * 16 + l8 + ((lane >> 3) & 1) * 8) * XSTRH
                     + ((lane >> 4) & 1) * 8) * 2;
#pragma unroll
    for (int p = 0; p < 2; p++)
        b_off[p] = ((wn + p * 16 + l8 + ((lane >> 4) & 1) * 8) * XSTRH
                    + ((lane >> 3) & 1) * 8) * 2;

    load_stage(0, 0);
    load_stage(1, BKH);
    for (int it = 0; it < NIT; ++it) {
        cpa_wait1();
        __syncthreads();
        if (it + NS1 - 1 < NIT) load_stage((it + NS1 - 1) % NS1, (it + NS1 - 1) * BKH);

        const uint32_t xb = sbase + (it % NS1) * STAGE1B;
        const uint32_t b1 = xb + TILE_B;
        const uint32_t bg = b1 + TILE_B;

#pragma unroll
        for (int kk = 0; kk < 4; kk++) {
            const int kb = kk * 32;
            uint32_t a[2][4];
#pragma unroll
            for (int mf = 0; mf < 2; mf++) LDSM4(a[mf], xb + a_off[mf] + kb);
#pragma unroll
            for (int p = 0; p < 2; p++) {
                uint32_t b[4], g[4];
                LDSM4(b, b1 + b_off[p] + kb);
                LDSM4(g, bg + b_off[p] + kb);
#pragma unroll
                for (int mf = 0; mf < 2; mf++) {
                    mma_f16(acc1[mf][2 * p],     a[mf], b[0], b[1]);
                    mma_f16(acc1[mf][2 * p + 1], a[mf], b[2], b[3]);
                    mma_f16(accg[mf][2 * p],     a[mf], g[0], g[1]);
                    mma_f16(accg[mf][2 * p + 1], a[mf], g[2], g[3]);
                }
            }
        }
    }

    __half* actp = g_acth[z];
#pragma unroll
    for (int mf = 0; mf < 2; mf++) {
        int r0 = m0 + wm + mf * 16 + qr;
        int r1 = r0 + 8;
#pragma unroll
        for (int nf = 0; nf < 4; nf++) {
            int cl = n0 + wn + nf * 8 + qk * 2;
            __half2 h0 = __floats2half2_rn(silu_f(acc1[mf][nf][0]) * accg[mf][nf][0],
                                           silu_f(acc1[mf][nf][1]) * accg[mf][nf][1]);
            __half2 h1 = __floats2half2_rn(silu_f(acc1[mf][nf][2]) * accg[mf][nf][2],
                                           silu_f(acc1[mf][nf][3]) * accg[mf][nf][3]);
            *(__half2*)(actp + (size_t)r0 * H_DIM + cl) = h0;
            *(__half2*)(actp + (size_t)r1 * H_DIM + cl) = h1;
        }
    }
}

// ============================================================================
// GEMM2 (fp16): y = act[z] @ W2[z];  z = zbase + blockIdx.z
// z < 7 -> g_y[z] fp16;  z = 7 -> g_ys fp16
// ============================================================================
__global__ void __launch_bounds__(NTHREADS, 1)
gemm2_all(int zbase) {
    extern __shared__ __half smemh[];
    const uint32_t sbase = (uint32_t)__cvta_generic_to_shared(smemh);
    const int z = zbase + blockIdx.z;

    const __half* Bp;
    int cnt;
    if (z < NEXP) { Bp = g_w2h + (size_t)z * H_DIM * D_DIM; cnt = g_cnt[z]; }
    else          { Bp = g_ws2h; cnt = T_TOK; }
    const __half* Ap = g_acth[z];

    const int m0 = blockIdx.x * BM2;
    if (m0 >= cnt) return;
    const int n0 = blockIdx.y * BN;
    const int tid = threadIdx.x;

    auto load_stage = [&](int s, int k0) {
        const uint32_t ab = sbase + s * STAGE2B;
        const uint32_t bb = ab + TILE_A2B;
#pragma unroll
        for (int i = 0; i < 4; i++) {
            int c = tid + i * NTHREADS;
            int r = c >> 3, j = c & 7;
            cpa16(ab + (r * XSTRH + j * 8) * 2,
                  Ap + (size_t)(m0 + r) * H_DIM + k0 + j * 8);
        }
#pragma unroll
        for (int i = 0; i < 2; i++) {
            int c = tid + i * NTHREADS;
            int r = c >> 3, j = c & 7;
            cpa16(bb + (r * XSTRH + j * 8) * 2,
                  Bp + (size_t)(n0 + r) * H_DIM + k0 + j * 8);
        }
        cpa_commit();
    };

    float acc[4][4][4];
#pragma unroll
    for (int i = 0; i < 4; i++)
#pragma unroll
        for (int j = 0; j < 4; j++)
#pragma unroll
            for (int r = 0; r < 4; r++) acc[i][j][r] = 0.f;

    const int wid = tid >> 5, lane = tid & 31;
    const int wm = (wid & 3) * 64, wn = (wid >> 2) * 32;
    const int qr = lane >> 2, qk = lane & 3;

    const int l8 = lane & 7;
    uint32_t a_off[4], b_off[2];
#pragma unroll
    for (int mf = 0; mf < 4; mf++)
        a_off[mf] = ((wm + mf * 16 + l8 + ((lane >> 3) & 1) * 8) * XSTRH
                     + ((lane >> 4) & 1) * 8) * 2;
#pragma unroll
    for (int p = 0; p < 2; p++)
        b_off[p] = ((wn + p * 16 + l8 + ((lane >> 4) & 1) * 8) * XSTRH
                    + ((lane >> 3) & 1) * 8) * 2;

    load_stage(0, 0);
    load_stage(1, BKH);
    for (int it = 0; it < NIT; ++it) {
        cpa_wait1();
        __syncthreads();
        if (it + NS2 - 1 < NIT) load_stage((it + NS2 - 1) % NS2, (it + NS2 - 1) * BKH);

        const uint32_t ab = sbase + (it % NS2) * STAGE2B;
        const uint32_t bb = ab + TILE_A2B;

#pragma unroll
        for (int kk = 0; kk < 4; kk++) {
            const int kb = kk * 32;
            uint32_t a[4][4];
#pragma unroll
            for (int mf = 0; mf < 4; mf++) LDSM4(a[mf], ab + a_off[mf] + kb);
#pragma unroll
            for (int p = 0; p < 2; p++) {
                uint32_t b[4];
                LDSM4(b, bb + b_off[p] + kb);
#pragma unroll
                for (int mf = 0; mf < 4; mf++) {
                    mma_f16(acc[mf][2 * p],     a[mf], b[0], b[1]);
                    mma_f16(acc[mf][2 * p + 1], a[mf], b[2], b[3]);
                }
            }
        }
    }

    __half* yp = (z == NEXP) ? g_ys : g_y[z];
#pragma unroll
    for (int mf = 0; mf < 4; mf++) {
        int r0 = m0 + wm + mf * 16 + qr;
        int r1 = r0 + 8;
#pragma unroll
        for (int nf = 0; nf < 4; nf++) {
            int cl = n0 + wn + nf * 8 + qk * 2;
            if (r0 < cnt)
                *(__half2*)(yp + (size_t)r0 * D_DIM + cl) =
                    __floats2half2_rn(acc[mf][nf][0], acc[mf][nf][1]);
            if (r1 < cnt)
                *(__half2*)(yp + (size_t)r1 * D_DIM + cl) =
                    __floats2half2_rn(acc[mf][nf][2], acc[mf][nf][3]);
        }
    }
}

// ============================================================================
// combine: out[t] = ys[t] + sum_k w_k * y[e_k][pos_k]   (all fp16 in, f32 out)
// ============================================================================
__global__ void __launch_bounds__(256) combine_kernel(float* __restrict__ out) {
    const int t = blockIdx.x;
    const int e0 = g_te[t][0], e1 = g_te[t][1], e2 = g_te[t][2];
    const float w0 = g_tw[t][0], w1 = g_tw[t][1], w2 = g_tw[t][2];
    const uint4* ys = (const uint4*)(g_ys + (size_t)t * D_DIM);
    const uint4* y0 = (const uint4*)(g_y[e0] + (size_t)g_tp[t][0] * D_DIM);
    const uint4* y1 = (const uint4*)(g_y[e1] + (size_t)g_tp[t][1] * D_DIM);
    const uint4* y2 = (const uint4*)(g_y[e2] + (size_t)g_tp[t][2] * D_DIM);
    float4* o = (float4*)(out + (size_t)t * D_DIM);

    const int i = threadIdx.x;
    uint4 s = ys[i], a = y0[i], b = y1[i], c = y2[i];
    const __half2* sh = (const __half2*)&s;
    const __half2* ah = (const __half2*)&a;
    const __half2* bh = (const __half2*)&b;
    const __half2* ch = (const __half2*)&c;

    float4 v0, v1;
    float2 f;
    f = __half22float2(sh[0]); v0.x = f.x; v0.y = f.y;
    f = __half22float2(sh[1]); v0.z = f.x; v0.w = f.y;
    f = __half22float2(sh[2]); v1.x = f.x; v1.y = f.y;
    f = __half22float2(sh[3]); v1.z = f.x; v1.w = f.y;

    f = __half22float2(ah[0]); v0.x += w0 * f.x; v0.y += w0 * f.y;
    f = __half22float2(ah[1]); v0.z += w0 * f.x; v0.w += w0 * f.y;
    f = __half22float2(ah[2]); v1.x += w0 * f.x; v1.y += w0 * f.y;
    f = __half22float2(ah[3]); v1.z += w0 * f.x; v1.w += w0 * f.y;

    f = __half22float2(bh[0]); v0.x += w1 * f.x; v0.y += w1 * f.y;
    f = __half22float2(bh[1]); v0.z += w1 * f.x; v0.w += w1 * f.y;
    f = __half22float2(bh[2]); v1.x += w1 * f.x; v1.y += w1 * f.y;
    f = __half22float2(bh[3]); v1.z += w1 * f.x; v1.w += w1 * f.y;

    f = __half22float2(ch[0]); v0.x += w2 * f.x; v0.y += w2 * f.y;
    f = __half22float2(ch[1]); v0.z += w2 * f.x; v0.w += w2 * f.y;
    f = __half22float2(ch[2]); v1.x += w2 * f.x; v1.y += w2 * f.y;
    f = __half22float2(ch[3]); v1.z += w2 * f.x; v1.w += w2 * f.y;

    o[i * 2]     = v0;
    o[i * 2 + 1] = v1;
}

// ============================================================================
// launcher — pipelined DAG with overlapped shared gemm2:
//   s2: zero -> gate_cvt
//   s1: cvtT_r1 -> cvtT_g2 -> [wait shared gemm1] -> gemm2(shared)  (|| routed gemm1)
//   main: cvtT_s1 -> [gate] -> gemm1(shared) -> [r1] -> gemm1(routed)
//         -> [g2] -> gemm2(routed) -> [shared gemm2 done] -> combine
// ============================================================================
extern "C" void kernel_launch(void* const* d_in, const int* in_sizes, int n_in,
                              void* d_out, int out_size) {
    const float* x    = (const float*)d_in[0];
    const float* W1   = (const float*)d_in[1];
    const float* Wg   = (const float*)d_in[2];
    const float* W2   = (const float*)d_in[3];
    const float* Ws1  = (const float*)d_in[4];
    const float* Wsg  = (const float*)d_in[5];
    const float* Ws2  = (const float*)d_in[6];
    const float* gw   = (const float*)d_in[7];
    const float* gb   = (const float*)d_in[8];
    const float* bias = (const float*)d_in[9];
    float* out = (float*)d_out;
    (void)in_sizes; (void)n_in; (void)out_size;

    cudaFuncSetAttribute(gemm1_all, cudaFuncAttributeMaxDynamicSharedMemorySize, SMEM1_BYTES);
    cudaFuncSetAttribute(gemm2_all, cudaFuncAttributeMaxDynamicSharedMemorySize, SMEM2_BYTES);

    __half *w1h, *wgh, *w2h, *ws1h, *wsgh, *ws2h;
    cudaGetSymbolAddress((void**)&w1h,  g_w1h);
    cudaGetSymbolAddress((void**)&wgh,  g_wgh);
    cudaGetSymbolAddress((void**)&w2h,  g_w2h);
    cudaGetSymbolAddress((void**)&ws1h, g_ws1h);
    cudaGetSymbolAddress((void**)&wsgh, g_wsgh);
    cudaGetSymbolAddress((void**)&ws2h, g_ws2h);

    static cudaStream_t s1 = nullptr, s2 = nullptr;
    static cudaEvent_t e0 = nullptr, eR1 = nullptr, eG2 = nullptr, eGate = nullptr;
    static cudaEvent_t eS1d = nullptr, eYS = nullptr;
    if (s1 == nullptr) {
        cudaStreamCreateWithFlags(&s1, cudaStreamNonBlocking);
        cudaStreamCreateWithFlags(&s2, cudaStreamNonBlocking);
        cudaEventCreateWithFlags(&e0,    cudaEventDisableTiming);
        cudaEventCreateWithFlags(&eR1,   cudaEventDisableTiming);
        cudaEventCreateWithFlags(&eG2,   cudaEventDisableTiming);
        cudaEventCreateWithFlags(&eGate, cudaEventDisableTiming);
        cudaEventCreateWithFlags(&eS1d,  cudaEventDisableTiming);
        cudaEventCreateWithFlags(&eYS,   cudaEventDisableTiming);
    }

    // fork
    cudaEventRecord(e0, 0);

    // s2: routing + x convert
    cudaStreamWaitEvent(s2, e0, 0);
    zero_cnt<<<1, 32, 0, s2>>>();
    gate_cvt<<<T_TOK, 256, 0, s2>>>(x, gw, gb, bias);
    cudaEventRecord(eGate, s2);

    // s1: routed gemm1 weights, then gemm2 weights
    cudaStreamWaitEvent(s1, e0, 0);
    cvtT_r1<<<dim3(32, 64, 14), 256, 0, s1>>>(W1, Wg, w1h, wgh);
    cudaEventRecord(eR1, s1);
    cvtT_g2<<<dim3(32, 64, 8), 256, 0, s1>>>(W2, Ws2, w2h, ws2h);
    cudaEventRecord(eG2, s1);

    // main: shared-expert weights, then shared gemm1 when x is ready
    cvtT_s1<<<dim3(32, 64, 2), 256>>>(Ws1, Wsg, ws1h, wsgh);
    cudaStreamWaitEvent(0, eGate, 0);
    gemm1_all<<<dim3(T_TOK / BM, H_DIM / BN, 1), NTHREADS, SMEM1_BYTES>>>(NEXP); // z = 7
    cudaEventRecord(eS1d, 0);

    // s1: shared gemm2 — overlaps routed gemm1 on main
    cudaStreamWaitEvent(s1, eS1d, 0);
    gemm2_all<<<dim3(T_TOK / BM2, D_DIM / BN, 1), NTHREADS, SMEM2_BYTES, s1>>>(NEXP);
    cudaEventRecord(eYS, s1);

    // main: routed gemm1 after its weights land
    cudaStreamWaitEvent(0, eR1, 0);
    gemm1_all<<<dim3(T_TOK / BM, H_DIM / BN, NEXP), NTHREADS, SMEM1_BYTES>>>(0); // z = 0..6

    // routed gemm2, then combine (after shared gemm2 done)
    cudaStreamWaitEvent(0, eG2, 0);
    gemm2_all<<<dim3(T_TOK / BM2, D_DIM / BN, NEXP), NTHREADS, SMEM2_BYTES>>>(0);
    cudaStreamWaitEvent(0, eYS, 0);
    combine_kernel<<<T_TOK, 256>>>(out);
}